// round 10
// baseline (speedup 1.0000x reference)
#include <cuda_runtime.h>
#include <cstdint>

#define NNODES 5000000
#define NGRAPHS 100000
#define NODES_PER_GRAPH 50

// L2-resident scratch (60 MB total).
__device__ int   g_deg[NNODES];  // edge count (self loop added as +1 at use sites)
__device__ float g_p[NNODES];    // xw[i] * dis[i]
__device__ float g_acc[NNODES];  // running scatter sum (init = p[i] == self-loop term)

// Grid-wide sense-reversing barrier state (re-entrant across graph replays:
// sense is read dynamically at each barrier; count self-resets to 0).
__device__ volatile int g_sense = 0;
__device__ int          g_count = 0;

__device__ __forceinline__ void grid_barrier(int nblk)
{
    __syncthreads();
    if (threadIdx.x == 0) {
        __threadfence();                      // make this block's writes visible
        int s = g_sense;
        if (atomicAdd(&g_count, 1) == nblk - 1) {
            g_count = 0;
            __threadfence();                  // count reset visible before flip
            g_sense = s ^ 1;                  // release
        } else {
            while (g_sense == s) { __nanosleep(128); }
            __threadfence();                  // acquire
        }
    }
    __syncthreads();
}

// dtype detect: int64 indices < 2^31 have all-zero high 32-bit words.
__device__ __forceinline__ int detect_is64(const unsigned long long* e)
{
    ulonglong2 a = *reinterpret_cast<const ulonglong2*>(e);
    ulonglong2 b = *reinterpret_cast<const ulonglong2*>(e + 2);
    return ((a.x >> 32) | (a.y >> 32) | (b.x >> 32) | (b.y >> 32)) == 0ull;
}

// ---------------------------------------------------------------------------
// Persistent megakernel: all phases with grid barriers between them.
__global__ void __launch_bounds__(256, 6)
k_all(const float* __restrict__ x,
      const long long* __restrict__ row64, const long long* __restrict__ col64,
      const int* __restrict__ row32,       const int* __restrict__ col32,
      const unsigned long long* __restrict__ ebase,
      const float* __restrict__ conv_w, const float* __restrict__ conv_b,
      const float* __restrict__ fc_w,   const float* __restrict__ fc_b,
      float* __restrict__ out, long long E, int nblk)
{
    const long long gtid = (long long)blockIdx.x * blockDim.x + threadIdx.x;
    const long long nth  = (long long)gridDim.x * blockDim.x;
    const int is64 = detect_is64(ebase);

    // ---- Phase 0: zero g_deg (int4-vectorized grid-stride) ----
    for (long long i = gtid; i < NNODES / 4; i += nth)
        reinterpret_cast<int4*>(g_deg)[i] = make_int4(0, 0, 0, 0);
    grid_barrier(nblk);

    // ---- Phase 1: degree count (RED.ADD to g_deg[col], 4 edges/step) ----
    {
        const long long nq = E >> 2;
        if (is64) {
            for (long long q = gtid; q < nq; q += nth) {
                long long base = q * 4;
                longlong2 a = *reinterpret_cast<const longlong2*>(col64 + base);
                longlong2 b = *reinterpret_cast<const longlong2*>(col64 + base + 2);
                atomicAdd(&g_deg[(int)a.x], 1);
                atomicAdd(&g_deg[(int)a.y], 1);
                atomicAdd(&g_deg[(int)b.x], 1);
                atomicAdd(&g_deg[(int)b.y], 1);
            }
            for (long long j = nq * 4 + gtid; j < E; j += nth)
                atomicAdd(&g_deg[(int)col64[j]], 1);
        } else {
            for (long long q = gtid; q < nq; q += nth) {
                int4 c = *reinterpret_cast<const int4*>(col32 + q * 4);
                atomicAdd(&g_deg[c.x], 1);
                atomicAdd(&g_deg[c.y], 1);
                atomicAdd(&g_deg[c.z], 1);
                atomicAdd(&g_deg[c.w], 1);
            }
            for (long long j = nq * 4 + gtid; j < E; j += nth)
                atomicAdd(&g_deg[col32[j]], 1);
        }
    }
    grid_barrier(nblk);

    // ---- Phase 2: prep. dis = rsqrt(deg+1); p = x*w*dis; acc = p ----
    {
        float w = conv_w[0];
        for (long long i = gtid; i < NNODES / 4; i += nth) {
            int4   d  = reinterpret_cast<const int4*>(g_deg)[i];
            float4 xv = reinterpret_cast<const float4*>(x)[i];
            float4 p;
            p.x = xv.x * w * rsqrtf((float)(d.x + 1));
            p.y = xv.y * w * rsqrtf((float)(d.y + 1));
            p.z = xv.z * w * rsqrtf((float)(d.z + 1));
            p.w = xv.w * w * rsqrtf((float)(d.w + 1));
            reinterpret_cast<float4*>(g_p)[i]   = p;
            reinterpret_cast<float4*>(g_acc)[i] = p;
        }
    }
    grid_barrier(nblk);

    // ---- Phase 3: edge scatter. acc[col] += p[row] ----
    {
        const long long nq = E >> 2;
        if (is64) {
            for (long long q = gtid; q < nq; q += nth) {
                long long base = q * 4;
                longlong2 r0 = *reinterpret_cast<const longlong2*>(row64 + base);
                longlong2 r1 = *reinterpret_cast<const longlong2*>(row64 + base + 2);
                longlong2 c0 = *reinterpret_cast<const longlong2*>(col64 + base);
                longlong2 c1 = *reinterpret_cast<const longlong2*>(col64 + base + 2);
                float p0 = __ldg(&g_p[(int)r0.x]);
                float p1 = __ldg(&g_p[(int)r0.y]);
                float p2 = __ldg(&g_p[(int)r1.x]);
                float p3 = __ldg(&g_p[(int)r1.y]);
                atomicAdd(&g_acc[(int)c0.x], p0);
                atomicAdd(&g_acc[(int)c0.y], p1);
                atomicAdd(&g_acc[(int)c1.x], p2);
                atomicAdd(&g_acc[(int)c1.y], p3);
            }
            for (long long j = nq * 4 + gtid; j < E; j += nth)
                atomicAdd(&g_acc[(int)col64[j]], __ldg(&g_p[(int)row64[j]]));
        } else {
            for (long long q = gtid; q < nq; q += nth) {
                int4 r = *reinterpret_cast<const int4*>(row32 + q * 4);
                int4 c = *reinterpret_cast<const int4*>(col32 + q * 4);
                float p0 = __ldg(&g_p[r.x]);
                float p1 = __ldg(&g_p[r.y]);
                float p2 = __ldg(&g_p[r.z]);
                float p3 = __ldg(&g_p[r.w]);
                atomicAdd(&g_acc[c.x], p0);
                atomicAdd(&g_acc[c.y], p1);
                atomicAdd(&g_acc[c.z], p2);
                atomicAdd(&g_acc[c.w], p3);
            }
            for (long long j = nq * 4 + gtid; j < E; j += nth)
                atomicAdd(&g_acc[col32[j]], __ldg(&g_p[row32[j]]));
        }
    }
    grid_barrier(nblk);

    // ---- Phase 4: h = rsqrt(deg+1)*acc + conv_b; per-graph FC (50 -> 2) ----
    {
        float b  = conv_b[0];
        float b0 = fc_b[0];
        float b1 = fc_b[1];
        for (long long g = gtid; g < NGRAPHS; g += nth) {
            float s0 = b0, s1 = b1;
            int base = (int)g * NODES_PER_GRAPH;
#pragma unroll
            for (int j = 0; j < NODES_PER_GRAPH; ++j) {
                float h = rsqrtf((float)(g_deg[base + j] + 1)) * g_acc[base + j] + b;
                s0 = fmaf(h, __ldg(&fc_w[j]), s0);
                s1 = fmaf(h, __ldg(&fc_w[NODES_PER_GRAPH + j]), s1);
            }
            out[2 * g]     = s0;
            out[2 * g + 1] = s1;
        }
    }
}

// ---------------------------------------------------------------------------
extern "C" void kernel_launch(void* const* d_in, const int* in_sizes, int n_in,
                              void* d_out, int out_size)
{
    // Resolve inputs BY SIZE. Sizes: x=5,000,000; edge_index=160,000,000
    // (elements, dtype int32 or int64 — detected on device);
    // conv_w=1; conv_b=1 (in appearance order); fc_w=100; fc_b=2.
    const float* x      = nullptr;
    const void*  eidx   = nullptr;
    const float* conv_w = nullptr;
    const float* conv_b = nullptr;
    const float* fc_w   = nullptr;
    const float* fc_b   = nullptr;
    long long    n_edge_elems = 0;

    for (int i = 0; i < n_in; ++i) {
        long long s = in_sizes[i];
        if (s == 160000000LL)      { eidx = d_in[i]; n_edge_elems = s; }
        else if (s == 5000000LL)   { x    = (const float*)d_in[i]; }
        else if (s == 100LL)       { fc_w = (const float*)d_in[i]; }
        else if (s == 2LL)         { fc_b = (const float*)d_in[i]; }
        else if (s == 1LL) {
            if (!conv_w) conv_w = (const float*)d_in[i];
            else         conv_b = (const float*)d_in[i];
        }
    }

    float* out = (float*)d_out;
    const long long E = n_edge_elems / 2;

    const long long* row64 = (const long long*)eidx;
    const long long* col64 = row64 + E;
    const int*       row32 = (const int*)eidx;
    const int*       col32 = row32 + E;
    const unsigned long long* ebase = (const unsigned long long*)eidx;

    // Co-resident grid: SMs x max-active-blocks (guarantees barrier liveness).
    int dev = 0, sms = 0, occ = 0;
    cudaGetDevice(&dev);
    cudaDeviceGetAttribute(&sms, cudaDevAttrMultiProcessorCount, dev);
    cudaOccupancyMaxActiveBlocksPerMultiprocessor(&occ, k_all, 256, 0);
    if (occ < 1) occ = 1;
    int nblk = sms * occ;

    k_all<<<nblk, 256>>>(x, row64, col64, row32, col32, ebase,
                         conv_w, conv_b, fc_w, fc_b, out, E, nblk);
}

// round 11
// speedup vs baseline: 1.4338x; 1.4338x over previous
#include <cuda_runtime.h>
#include <cstdint>

#define NNODES 5000000
#define NGRAPHS 100000
#define NODES_PER_GRAPH 50

// L2-resident scratch (60 MB total).
__device__ int   g_deg[NNODES];  // edge count (self loop added as +1 at use sites)
__device__ float g_p[NNODES];    // phase1: x*w ; phase2 onward: x*w*dis
__device__ float g_acc[NNODES];  // running scatter sum (init = p[i] == self-loop term)

// Per-thread dtype detect: int64 indices < 2^31 have all-zero high words.
__device__ __forceinline__ int detect_is64(const unsigned long long* e)
{
    ulonglong2 a = *reinterpret_cast<const ulonglong2*>(e);
    ulonglong2 b = *reinterpret_cast<const ulonglong2*>(e + 2);
    return ((a.x >> 32) | (a.y >> 32) | (b.x >> 32) | (b.y >> 32)) == 0ull;
}

// ---------------------------------------------------------------------------
// 1) degree count: RED.ADD to g_deg[col]. 4 edges/thread. (At L2-slice floor.)
//    Additionally, the first NNODES/4 threads stream xw = x*conv_w into g_p —
//    pure DRAM-read work that hides under the atomic phase (DRAM is ~15% busy).
__global__ void __launch_bounds__(256, 8)
k_count(const long long* __restrict__ col64,
        const int* __restrict__ col32,
        const unsigned long long* __restrict__ ebase,
        const float* __restrict__ x,
        const float* __restrict__ conv_w, long long E)
{
    long long t    = (long long)blockIdx.x * blockDim.x + threadIdx.x;
    long long base = t * 4;
    if (detect_is64(ebase)) {
        if (base + 3 < E) {
            longlong2 a = *reinterpret_cast<const longlong2*>(col64 + base);
            longlong2 b = *reinterpret_cast<const longlong2*>(col64 + base + 2);
            atomicAdd(&g_deg[(int)a.x], 1);
            atomicAdd(&g_deg[(int)a.y], 1);
            atomicAdd(&g_deg[(int)b.x], 1);
            atomicAdd(&g_deg[(int)b.y], 1);
        } else {
            for (long long j = base; j < E; ++j)
                atomicAdd(&g_deg[(int)col64[j]], 1);
        }
    } else {
        if (base + 3 < E) {
            int4 c = *reinterpret_cast<const int4*>(col32 + base);
            atomicAdd(&g_deg[c.x], 1);
            atomicAdd(&g_deg[c.y], 1);
            atomicAdd(&g_deg[c.z], 1);
            atomicAdd(&g_deg[c.w], 1);
        } else {
            for (long long j = base; j < E; ++j)
                atomicAdd(&g_deg[col32[j]], 1);
        }
    }
    // Streamed xw precompute (first 1.25M threads, one float4 each).
    if (t < NNODES / 4) {
        float w = conv_w[0];
        float4 xv = reinterpret_cast<const float4*>(x)[t];
        xv.x *= w; xv.y *= w; xv.z *= w; xv.w *= w;
        reinterpret_cast<float4*>(g_p)[t] = xv;
    }
}

// ---------------------------------------------------------------------------
// 2) per-node prep, 4 nodes/thread vectorized:
//    p = xw * rsqrt(deg+1); acc starts at p (self-loop term).
//    Reads g_p (L2-resident, written by k_count) instead of x (DRAM).
__global__ void k_prep()
{
    int i = blockIdx.x * blockDim.x + threadIdx.x;  // quad index
    const int n4 = NNODES / 4;                       // 1,250,000 (exact)
    if (i >= n4) return;
    int4   d  = reinterpret_cast<const int4*>(g_deg)[i];
    float4 xw = reinterpret_cast<const float4*>(g_p)[i];
    float4 p;
    p.x = xw.x * rsqrtf((float)(d.x + 1));
    p.y = xw.y * rsqrtf((float)(d.y + 1));
    p.z = xw.z * rsqrtf((float)(d.z + 1));
    p.w = xw.w * rsqrtf((float)(d.w + 1));
    reinterpret_cast<float4*>(g_p)[i]   = p;
    reinterpret_cast<float4*>(g_acc)[i] = p;
}

// ---------------------------------------------------------------------------
// 3) edge scatter: acc[col] += p[row]. One 4B gather + one 4B RED per edge.
//    (At L2-slice floor — byte-identical structure to the 960 µs build.)
__global__ void __launch_bounds__(256, 8)
k_edge(const long long* __restrict__ row64,
       const long long* __restrict__ col64,
       const int* __restrict__ row32,
       const int* __restrict__ col32,
       const unsigned long long* __restrict__ ebase, long long E)
{
    long long t    = (long long)blockIdx.x * blockDim.x + threadIdx.x;
    long long base = t * 4;
    if (detect_is64(ebase)) {
        if (base + 3 < E) {
            longlong2 r0 = *reinterpret_cast<const longlong2*>(row64 + base);
            longlong2 r1 = *reinterpret_cast<const longlong2*>(row64 + base + 2);
            longlong2 c0 = *reinterpret_cast<const longlong2*>(col64 + base);
            longlong2 c1 = *reinterpret_cast<const longlong2*>(col64 + base + 2);
            float p0 = __ldg(&g_p[(int)r0.x]);
            float p1 = __ldg(&g_p[(int)r0.y]);
            float p2 = __ldg(&g_p[(int)r1.x]);
            float p3 = __ldg(&g_p[(int)r1.y]);
            atomicAdd(&g_acc[(int)c0.x], p0);
            atomicAdd(&g_acc[(int)c0.y], p1);
            atomicAdd(&g_acc[(int)c1.x], p2);
            atomicAdd(&g_acc[(int)c1.y], p3);
        } else {
            for (long long j = base; j < E; ++j)
                atomicAdd(&g_acc[(int)col64[j]], __ldg(&g_p[(int)row64[j]]));
        }
    } else {
        if (base + 3 < E) {
            int4 r = *reinterpret_cast<const int4*>(row32 + base);
            int4 c = *reinterpret_cast<const int4*>(col32 + base);
            float p0 = __ldg(&g_p[r.x]);
            float p1 = __ldg(&g_p[r.y]);
            float p2 = __ldg(&g_p[r.z]);
            float p3 = __ldg(&g_p[r.w]);
            atomicAdd(&g_acc[c.x], p0);
            atomicAdd(&g_acc[c.y], p1);
            atomicAdd(&g_acc[c.z], p2);
            atomicAdd(&g_acc[c.w], p3);
        } else {
            for (long long j = base; j < E; ++j)
                atomicAdd(&g_acc[col32[j]], __ldg(&g_p[row32[j]]));
        }
    }
}

// ---------------------------------------------------------------------------
// 4) fused h = rsqrt(deg+1)*acc + conv_b  and per-graph FC (50 -> 2).
//    One thread per TWO graphs (100 nodes) so int4/float4 loads stay aligned.
__global__ void k_fc(const float* __restrict__ conv_b,
                     const float* __restrict__ fc_w,   // [2,50] row-major
                     const float* __restrict__ fc_b,   // [2]
                     float* __restrict__ out)          // [NGRAPHS,2]
{
    int t = blockIdx.x * blockDim.x + threadIdx.x;     // graph pair index
    const int npairs = NGRAPHS / 2;                    // 50,000
    if (t >= npairs) return;
    float b   = conv_b[0];
    float fb0 = fc_b[0];
    float fb1 = fc_b[1];
    int base = t * 2 * NODES_PER_GRAPH;                // multiple of 4

    float h[100];
#pragma unroll
    for (int q = 0; q < 25; ++q) {
        int4   d = reinterpret_cast<const int4*>(g_deg + base)[q];
        float4 a = reinterpret_cast<const float4*>(g_acc + base)[q];
        h[4 * q]     = rsqrtf((float)(d.x + 1)) * a.x + b;
        h[4 * q + 1] = rsqrtf((float)(d.y + 1)) * a.y + b;
        h[4 * q + 2] = rsqrtf((float)(d.z + 1)) * a.z + b;
        h[4 * q + 3] = rsqrtf((float)(d.w + 1)) * a.w + b;
    }
    float s00 = fb0, s01 = fb1, s10 = fb0, s11 = fb1;
#pragma unroll
    for (int j = 0; j < NODES_PER_GRAPH; ++j) {
        float w0 = __ldg(&fc_w[j]);
        float w1 = __ldg(&fc_w[NODES_PER_GRAPH + j]);
        s00 = fmaf(h[j],       w0, s00);
        s01 = fmaf(h[j],       w1, s01);
        s10 = fmaf(h[50 + j],  w0, s10);
        s11 = fmaf(h[50 + j],  w1, s11);
    }
    reinterpret_cast<float4*>(out)[t] = make_float4(s00, s01, s10, s11);
}

// ---------------------------------------------------------------------------
extern "C" void kernel_launch(void* const* d_in, const int* in_sizes, int n_in,
                              void* d_out, int out_size)
{
    // Resolve inputs BY SIZE. Sizes: x=5,000,000; edge_index=160,000,000
    // (elements, dtype int32 or int64 — detected on device);
    // conv_w=1; conv_b=1 (in appearance order); fc_w=100; fc_b=2.
    const float* x      = nullptr;
    const void*  eidx   = nullptr;
    const float* conv_w = nullptr;
    const float* conv_b = nullptr;
    const float* fc_w   = nullptr;
    const float* fc_b   = nullptr;
    long long    n_edge_elems = 0;

    for (int i = 0; i < n_in; ++i) {
        long long s = in_sizes[i];
        if (s == 160000000LL)      { eidx = d_in[i]; n_edge_elems = s; }
        else if (s == 5000000LL)   { x    = (const float*)d_in[i]; }
        else if (s == 100LL)       { fc_w = (const float*)d_in[i]; }
        else if (s == 2LL)         { fc_b = (const float*)d_in[i]; }
        else if (s == 1LL) {
            if (!conv_w) conv_w = (const float*)d_in[i];
            else         conv_b = (const float*)d_in[i];
        }
    }

    float* out = (float*)d_out;
    const long long E = n_edge_elems / 2;

    const long long* row64 = (const long long*)eidx;
    const long long* col64 = row64 + E;
    const int*       row32 = (const int*)eidx;
    const int*       col32 = row32 + E;
    const unsigned long long* ebase = (const unsigned long long*)eidx;

    const int TPB = 256;
    int prep_blocks = (NNODES / 4 + TPB - 1) / TPB;
    int edge_blocks = (int)((E + (long long)TPB * 4 - 1) / ((long long)TPB * 4));
    int fc_blocks   = (NGRAPHS / 2 + TPB - 1) / TPB;

    // Zero the degree array with a memset node (graph-capturable, no alloc).
    void* deg_ptr = nullptr;
    cudaGetSymbolAddress(&deg_ptr, g_deg);
    cudaMemsetAsync(deg_ptr, 0, (size_t)NNODES * sizeof(int), 0);

    k_count<<<edge_blocks, TPB>>>(col64, col32, ebase, x, conv_w, E);
    k_prep <<<prep_blocks, TPB>>>();
    k_edge <<<edge_blocks, TPB>>>(row64, col64, row32, col32, ebase, E);
    k_fc   <<<fc_blocks,   TPB>>>(conv_b, fc_w, fc_b, out);
}

// round 12
// speedup vs baseline: 1.4383x; 1.0031x over previous
#include <cuda_runtime.h>
#include <cstdint>

#define NNODES 5000000
#define NGRAPHS 100000
#define NODES_PER_GRAPH 50

// L2-resident scratch (60 MB total). g_deg is zero-initialized at load and
// re-zeroed by k_fc at the end of every run (deterministic across replays).
__device__ int   g_deg[NNODES];  // edge count (self loop added as +1 at use sites)
__device__ float g_p[NNODES];    // phase1: x*w ; phase2 onward: x*w*dis
__device__ float g_acc[NNODES];  // running scatter sum (init = p[i] == self-loop term)

// Per-thread dtype detect: int64 indices < 2^31 have all-zero high words.
__device__ __forceinline__ int detect_is64(const unsigned long long* e)
{
    ulonglong2 a = *reinterpret_cast<const ulonglong2*>(e);
    ulonglong2 b = *reinterpret_cast<const ulonglong2*>(e + 2);
    return ((a.x >> 32) | (a.y >> 32) | (b.x >> 32) | (b.y >> 32)) == 0ull;
}

// ---------------------------------------------------------------------------
// 1) degree count: RED.ADD to g_deg[col]. 4 edges/thread. (At L2-slice floor.)
//    First NNODES/4 threads also stream xw = x*conv_w into g_p (free DRAM work).
__global__ void __launch_bounds__(256, 8)
k_count(const long long* __restrict__ col64,
        const int* __restrict__ col32,
        const unsigned long long* __restrict__ ebase,
        const float* __restrict__ x,
        const float* __restrict__ conv_w, long long E)
{
    long long t    = (long long)blockIdx.x * blockDim.x + threadIdx.x;
    long long base = t * 4;
    if (detect_is64(ebase)) {
        if (base + 3 < E) {
            longlong2 a = *reinterpret_cast<const longlong2*>(col64 + base);
            longlong2 b = *reinterpret_cast<const longlong2*>(col64 + base + 2);
            atomicAdd(&g_deg[(int)a.x], 1);
            atomicAdd(&g_deg[(int)a.y], 1);
            atomicAdd(&g_deg[(int)b.x], 1);
            atomicAdd(&g_deg[(int)b.y], 1);
        } else {
            for (long long j = base; j < E; ++j)
                atomicAdd(&g_deg[(int)col64[j]], 1);
        }
    } else {
        if (base + 3 < E) {
            int4 c = *reinterpret_cast<const int4*>(col32 + base);
            atomicAdd(&g_deg[c.x], 1);
            atomicAdd(&g_deg[c.y], 1);
            atomicAdd(&g_deg[c.z], 1);
            atomicAdd(&g_deg[c.w], 1);
        } else {
            for (long long j = base; j < E; ++j)
                atomicAdd(&g_deg[col32[j]], 1);
        }
    }
    if (t < NNODES / 4) {
        float w = conv_w[0];
        float4 xv = reinterpret_cast<const float4*>(x)[t];
        xv.x *= w; xv.y *= w; xv.z *= w; xv.w *= w;
        reinterpret_cast<float4*>(g_p)[t] = xv;
    }
}

// ---------------------------------------------------------------------------
// 2) per-node prep (PDL follower): p = xw * rsqrt(deg+1); acc = p.
__global__ void k_prep()
{
    int i = blockIdx.x * blockDim.x + threadIdx.x;  // quad index
    const int n4 = NNODES / 4;                       // 1,250,000 (exact)
    cudaGridDependencySynchronize();                 // wait k_count writes
    if (i >= n4) return;
    int4   d  = reinterpret_cast<const int4*>(g_deg)[i];
    float4 xw = reinterpret_cast<const float4*>(g_p)[i];
    float4 p;
    p.x = xw.x * rsqrtf((float)(d.x + 1));
    p.y = xw.y * rsqrtf((float)(d.y + 1));
    p.z = xw.z * rsqrtf((float)(d.z + 1));
    p.w = xw.w * rsqrtf((float)(d.w + 1));
    reinterpret_cast<float4*>(g_p)[i]   = p;
    reinterpret_cast<float4*>(g_acc)[i] = p;
}

// ---------------------------------------------------------------------------
// 3) edge scatter (PDL follower): acc[col] += p[row].
//    Edge-index loads are upstream-independent -> issued BEFORE the dependency
//    sync so their latency hides under k_prep's tail.
__global__ void __launch_bounds__(256, 8)
k_edge(const long long* __restrict__ row64,
       const long long* __restrict__ col64,
       const int* __restrict__ row32,
       const int* __restrict__ col32,
       const unsigned long long* __restrict__ ebase, long long E)
{
    long long t    = (long long)blockIdx.x * blockDim.x + threadIdx.x;
    long long base = t * 4;
    if (detect_is64(ebase)) {
        if (base + 3 < E) {
            longlong2 r0 = *reinterpret_cast<const longlong2*>(row64 + base);
            longlong2 r1 = *reinterpret_cast<const longlong2*>(row64 + base + 2);
            longlong2 c0 = *reinterpret_cast<const longlong2*>(col64 + base);
            longlong2 c1 = *reinterpret_cast<const longlong2*>(col64 + base + 2);
            cudaGridDependencySynchronize();         // wait k_prep (g_p, g_acc)
            float p0 = __ldg(&g_p[(int)r0.x]);
            float p1 = __ldg(&g_p[(int)r0.y]);
            float p2 = __ldg(&g_p[(int)r1.x]);
            float p3 = __ldg(&g_p[(int)r1.y]);
            atomicAdd(&g_acc[(int)c0.x], p0);
            atomicAdd(&g_acc[(int)c0.y], p1);
            atomicAdd(&g_acc[(int)c1.x], p2);
            atomicAdd(&g_acc[(int)c1.y], p3);
        } else {
            cudaGridDependencySynchronize();
            for (long long j = base; j < E; ++j)
                atomicAdd(&g_acc[(int)col64[j]], __ldg(&g_p[(int)row64[j]]));
        }
    } else {
        if (base + 3 < E) {
            int4 r = *reinterpret_cast<const int4*>(row32 + base);
            int4 c = *reinterpret_cast<const int4*>(col32 + base);
            cudaGridDependencySynchronize();         // wait k_prep (g_p, g_acc)
            float p0 = __ldg(&g_p[r.x]);
            float p1 = __ldg(&g_p[r.y]);
            float p2 = __ldg(&g_p[r.z]);
            float p3 = __ldg(&g_p[r.w]);
            atomicAdd(&g_acc[c.x], p0);
            atomicAdd(&g_acc[c.y], p1);
            atomicAdd(&g_acc[c.z], p2);
            atomicAdd(&g_acc[c.w], p3);
        } else {
            cudaGridDependencySynchronize();
            for (long long j = base; j < E; ++j)
                atomicAdd(&g_acc[col32[j]], __ldg(&g_p[row32[j]]));
        }
    }
}

// ---------------------------------------------------------------------------
// 4) fused h = rsqrt(deg+1)*acc + conv_b and per-graph FC (PDL follower).
//    One thread per TWO graphs (100 nodes). After its last read, each thread
//    re-zeros its exclusive g_deg range for the next replay (replaces memset).
__global__ void k_fc(const float* __restrict__ conv_b,
                     const float* __restrict__ fc_w,   // [2,50] row-major
                     const float* __restrict__ fc_b,   // [2]
                     float* __restrict__ out)          // [NGRAPHS,2]
{
    int t = blockIdx.x * blockDim.x + threadIdx.x;     // graph pair index
    const int npairs = NGRAPHS / 2;                    // 50,000
    cudaGridDependencySynchronize();                   // wait k_edge (g_acc)
    if (t >= npairs) return;
    float b   = conv_b[0];
    float fb0 = fc_b[0];
    float fb1 = fc_b[1];
    int base = t * 2 * NODES_PER_GRAPH;                // multiple of 4

    float h[100];
#pragma unroll
    for (int q = 0; q < 25; ++q) {
        int4   d = reinterpret_cast<const int4*>(g_deg + base)[q];
        float4 a = reinterpret_cast<const float4*>(g_acc + base)[q];
        h[4 * q]     = rsqrtf((float)(d.x + 1)) * a.x + b;
        h[4 * q + 1] = rsqrtf((float)(d.y + 1)) * a.y + b;
        h[4 * q + 2] = rsqrtf((float)(d.z + 1)) * a.z + b;
        h[4 * q + 3] = rsqrtf((float)(d.w + 1)) * a.w + b;
    }
    // Re-zero this thread's exclusive g_deg range for the next run.
#pragma unroll
    for (int q = 0; q < 25; ++q)
        reinterpret_cast<int4*>(g_deg + base)[q] = make_int4(0, 0, 0, 0);

    float s00 = fb0, s01 = fb1, s10 = fb0, s11 = fb1;
#pragma unroll
    for (int j = 0; j < NODES_PER_GRAPH; ++j) {
        float w0 = __ldg(&fc_w[j]);
        float w1 = __ldg(&fc_w[NODES_PER_GRAPH + j]);
        s00 = fmaf(h[j],       w0, s00);
        s01 = fmaf(h[j],       w1, s01);
        s10 = fmaf(h[50 + j],  w0, s10);
        s11 = fmaf(h[50 + j],  w1, s11);
    }
    reinterpret_cast<float4*>(out)[t] = make_float4(s00, s01, s10, s11);
}

// ---------------------------------------------------------------------------
static void launch_pdl(void* func, dim3 grid, dim3 block,
                       void** args, bool pdl)
{
    cudaLaunchConfig_t cfg = {};
    cfg.gridDim  = grid;
    cfg.blockDim = block;
    cfg.stream   = 0;
    cudaLaunchAttribute attr[1];
    if (pdl) {
        attr[0].id = cudaLaunchAttributeProgrammaticStreamSerialization;
        attr[0].val.programmaticStreamSerializationAllowed = 1;
        cfg.attrs = attr;
        cfg.numAttrs = 1;
    }
    cudaLaunchKernelExC(&cfg, func, args);
}

extern "C" void kernel_launch(void* const* d_in, const int* in_sizes, int n_in,
                              void* d_out, int out_size)
{
    // Resolve inputs BY SIZE. Sizes: x=5,000,000; edge_index=160,000,000
    // (elements, dtype int32 or int64 — detected on device);
    // conv_w=1; conv_b=1 (in appearance order); fc_w=100; fc_b=2.
    const float* x      = nullptr;
    const void*  eidx   = nullptr;
    const float* conv_w = nullptr;
    const float* conv_b = nullptr;
    const float* fc_w   = nullptr;
    const float* fc_b   = nullptr;
    long long    n_edge_elems = 0;

    for (int i = 0; i < n_in; ++i) {
        long long s = in_sizes[i];
        if (s == 160000000LL)      { eidx = d_in[i]; n_edge_elems = s; }
        else if (s == 5000000LL)   { x    = (const float*)d_in[i]; }
        else if (s == 100LL)       { fc_w = (const float*)d_in[i]; }
        else if (s == 2LL)         { fc_b = (const float*)d_in[i]; }
        else if (s == 1LL) {
            if (!conv_w) conv_w = (const float*)d_in[i];
            else         conv_b = (const float*)d_in[i];
        }
    }

    float* out = (float*)d_out;
    long long E = n_edge_elems / 2;

    const long long* row64 = (const long long*)eidx;
    const long long* col64 = row64 + E;
    const int*       row32 = (const int*)eidx;
    const int*       col32 = row32 + E;
    const unsigned long long* ebase = (const unsigned long long*)eidx;

    const int TPB = 256;
    dim3 blk(TPB);
    dim3 prep_grid((NNODES / 4 + TPB - 1) / TPB);
    dim3 edge_grid((unsigned)((E + (long long)TPB * 4 - 1) / ((long long)TPB * 4)));
    dim3 fc_grid((NGRAPHS / 2 + TPB - 1) / TPB);

    {   // k_count (no PDL — first kernel; g_deg zeroed by prior k_fc / load-init)
        void* args[] = {(void*)&col64, (void*)&col32, (void*)&ebase,
                        (void*)&x, (void*)&conv_w, (void*)&E};
        launch_pdl((void*)k_count, edge_grid, blk, args, false);
    }
    {   // k_prep (PDL)
        void* args[] = {};
        launch_pdl((void*)k_prep, prep_grid, blk, args, true);
    }
    {   // k_edge (PDL)
        void* args[] = {(void*)&row64, (void*)&col64, (void*)&row32,
                        (void*)&col32, (void*)&ebase, (void*)&E};
        launch_pdl((void*)k_edge, edge_grid, blk, args, true);
    }
    {   // k_fc (PDL)
        void* args[] = {(void*)&conv_b, (void*)&fc_w, (void*)&fc_b, (void*)&out};
        launch_pdl((void*)k_fc, fc_grid, blk, args, true);
    }
}